// round 8
// baseline (speedup 1.0000x reference)
#include <cuda_runtime.h>
#include <cuda_bf16.h>

// Problem geometry: [B=4, 1, D=160, H=160, W=160]
#define NB 4
#define S  160
#define PLANE4      6400           // float4/int4 per (b,d) plane
#define PLANE_ELEMS 25600
#define NPLANES     640
#define MAIN_CHUNKS 5120           // fallback mask chunks (8 per plane)
#define CHUNK4      800
#define NBLOCKS_B   592            // 4/SM -> all co-resident (safe spin)
#define TOTAL_ELEMS (4.0 * 160.0 * 160.0 * 160.0)

// ---- device scratch (zero at load; kB's last block re-zeroes everything) ----
__device__ unsigned char g_winD[NB][8];   // slab any-flags: 0..3 low end, 4..7 high end
__device__ unsigned char g_winH[NB][8];
__device__ unsigned char g_winW[NB][8];
__device__ unsigned char g_any[NB][3][S]; // full projections (fallback only)
__device__ int      g_lo[NB][3];
__device__ int      g_hi[NB][3];
__device__ int      g_fallback;
__device__ int      g_ready;
__device__ double   g_ss_all;
__device__ double   g_ss_out;
__device__ unsigned g_done_A, g_done_pB, g_done_B;

// Exact f32 replication of the reference bbox math (mn<0 -> empty box).
__device__ __forceinline__ void bbox_from(int mn, int mx, int* lo, int* hi) {
    if (mn < 0) { *lo = 0; *hi = 0; return; }
    float c = ((float)mx + (float)mn) * 0.5f;
    float e = ((float)mx - (float)mn + 1.0f) * 0.5f * 1.2f;   // EXPAND
    *lo = (int)fmaxf(0.0f, floorf(c - e));
    *hi = (int)fminf((float)(S - 1), floorf(c + e));          // EXCLUSIVE
}

// ===================== kernel A: SS_all + per-plane mask boundary windows ====
// One block per (b,d) plane, 640 x 256 (the best-measured BW shape). Each
// block: (1) unweighted SS over its pred/true plane; (2) H window = rows
// {0..3,156..159} of its mask plane; (3) W window = first/last int4 of each
// of its 160 mask rows; (4) if its d is in {0..3,156..159}, an any-scan of
// the whole mask plane for the D window. Flag stores are benign races (all
// writers store 1). Last-done block derives the bbox from the window flags,
// or sets g_fallback if an axis end is unresolved.
__global__ __launch_bounds__(256) void kA(const float* __restrict__ pred,
                                          const float* __restrict__ truth,
                                          const int*   __restrict__ mask) {
    __shared__ int sw[8];                // W-window component flags
    __shared__ double warpSum[8];
    __shared__ int sLast;

    const int p   = blockIdx.x;          // 0..639
    const int b   = p / S;
    const int d   = p - b * S;
    const int tid = threadIdx.x;

    if (tid < 8) sw[tid] = 0;
    __syncthreads();

    // ---- (1) unweighted SS over this plane (25 iters, stride 256) ----
    const float4* P = (const float4*)pred  + (size_t)p * PLANE4;
    const float4* T = (const float4*)truth + (size_t)p * PLANE4;
    float acc = 0.0f;
    #pragma unroll 5
    for (int i = tid; i < PLANE4; i += 256) {
        float4 pv = P[i];
        float4 tv = T[i];
        float dx = pv.x - tv.x, dy = pv.y - tv.y, dz = pv.z - tv.z, dw = pv.w - tv.w;
        acc = fmaf(dx, dx, acc);
        acc = fmaf(dy, dy, acc);
        acc = fmaf(dz, dz, acc);
        acc = fmaf(dw, dw, acc);
    }

    const int4* M = (const int4*)mask + (size_t)p * PLANE4;

    // ---- (2) H window: rows 0..3 (quads 0..159) and 156..159 (6240..6399) --
    if (tid < 160) {
        int4 va = M[tid];
        int4 vb = M[6240 + tid];
        if (va.x | va.y | va.z | va.w) g_winH[b][tid / 40]     = 1;
        if (vb.x | vb.y | vb.z | vb.w) g_winH[b][4 + tid / 40] = 1;
    }

    // ---- (3) W window: first/last int4 of each row (row = tid) ----
    if (tid < 160) {
        int4 v0 = M[tid * 40];           // w 0..3
        int4 v1 = M[tid * 40 + 39];      // w 156..159
        if (v0.x) sw[0] = 1;
        if (v0.y) sw[1] = 1;
        if (v0.z) sw[2] = 1;
        if (v0.w) sw[3] = 1;
        if (v1.x) sw[4] = 1;
        if (v1.y) sw[5] = 1;
        if (v1.z) sw[6] = 1;
        if (v1.w) sw[7] = 1;
    }

    // ---- (4) D window: this plane is one of the 8 boundary slabs ----
    if (d < 4 || d >= 156) {
        int o = 0;
        for (int i = tid; i < PLANE4; i += 256) {
            int4 v = M[i];
            o |= v.x | v.y | v.z | v.w;
        }
        if (__syncthreads_or(o)) {
            if (tid == 0) g_winD[b][(d < 4) ? d : d - 152] = 1;
        }
    }
    __syncthreads();
    if (tid < 8 && sw[tid]) g_winW[b][tid] = 1;

    // ---- block reduce SS -> one double atomic ----
    #pragma unroll
    for (int off = 16; off > 0; off >>= 1)
        acc += __shfl_xor_sync(0xFFFFFFFFu, acc, off);
    if ((tid & 31) == 0) warpSum[tid >> 5] = (double)acc;
    __syncthreads();
    if (tid == 0) {
        double s = 0.0;
        #pragma unroll
        for (int w = 0; w < 8; w++) s += warpSum[w];
        atomicAdd(&g_ss_all, s);
    }

    // ---- last-done block: bbox from window flags (or fallback) ----
    __threadfence();
    if (tid == 0) sLast = (atomicAdd(&g_done_A, 1u) == (unsigned)(NPLANES - 1));
    __syncthreads();
    if (sLast && tid == 0) {
        int fb = 0;
        for (int bb = 0; bb < NB; bb++) {
            volatile unsigned char* wA[3] = { g_winD[bb], g_winH[bb], g_winW[bb] };
            int mn[3], mx[3], ok = 1;
            for (int ax = 0; ax < 3; ax++) {
                int m0 = -1, m1 = -1;
                for (int k = 0; k < 4; k++)  if (wA[ax][k] && m0 < 0) m0 = k;
                for (int k = 7; k >= 4; k--) if (wA[ax][k] && m1 < 0) m1 = 152 + k;
                mn[ax] = m0; mx[ax] = m1;
                if (m0 < 0 || m1 < 0) ok = 0;    // end unresolved -> fallback
            }
            if (ok) {
                for (int ax = 0; ax < 3; ax++) {
                    int lo, hi;
                    bbox_from(mn[ax], mx[ax], &lo, &hi);
                    g_lo[bb][ax] = lo; g_hi[bb][ax] = hi;
                }
            } else {
                fb = 1;
            }
        }
        g_fallback = fb;
    }
}

// ===================== kernel B: SS_out (+rare fallback) + finalize =========
// 592 blocks x 256 (4/SM => co-resident: internal spin safe on the rare
// fallback path). Grid-stride over 5120 (plane, seg) items: fully-outside
// planes are split 8 ways (800 quads/seg); inside planes' small boundary
// work (H rows + W stubs) runs on seg 0 only.
__global__ __launch_bounds__(256, 4) void kB(const float* __restrict__ pred,
                                             const float* __restrict__ truth,
                                             const int*   __restrict__ mask,
                                             float* __restrict__ out) {
    __shared__ double warpSum[8];
    __shared__ int sLast;
    const int tid = threadIdx.x;

    if (g_fallback) {
        // ---- rare: full mask projection, then bbox, then grid-wide spin ----
        const int rg = tid / 40, c = tid % 40;
        for (int chunk = blockIdx.x; chunk < MAIN_CHUNKS; chunk += NBLOCKS_B) {
            if (tid < 160) {
                int plane = chunk >> 3, part = chunk & 7;
                int b = plane / S, d = plane - b * S;
                const int4* M = (const int4*)mask + plane * PLANE4 + part * CHUNK4 + tid;
                int4 o = make_int4(0, 0, 0, 0);
                #pragma unroll
                for (int k = 0; k < 5; k++) {
                    int4 v = M[160 * k];
                    o.x |= v.x; o.y |= v.y; o.z |= v.z; o.w |= v.w;
                    if (v.x | v.y | v.z | v.w) {
                        g_any[b][1][part * 20 + rg + 4 * k] = 1;
                        g_any[b][0][d] = 1;
                    }
                }
                if (o.x) g_any[b][2][c * 4 + 0] = 1;
                if (o.y) g_any[b][2][c * 4 + 1] = 1;
                if (o.z) g_any[b][2][c * 4 + 2] = 1;
                if (o.w) g_any[b][2][c * 4 + 3] = 1;
            }
        }
        __threadfence();
        if (tid == 0) {
            if (atomicAdd(&g_done_pB, 1u) == (unsigned)(NBLOCKS_B - 1)) {
                for (int b = 0; b < NB; b++)
                    for (int ax = 0; ax < 3; ax++) {
                        volatile unsigned char* a = &g_any[b][ax][0];
                        int mn = -1, mx = -1;
                        for (int i = 0; i < S; i++)
                            if (a[i]) { if (mn < 0) mn = i; mx = i; }
                        int lo, hi;
                        bbox_from(mn, mx, &lo, &hi);
                        g_lo[b][ax] = lo; g_hi[b][ax] = hi;
                    }
                __threadfence();
                *(volatile int*)&g_ready = 1;
            }
            while (!*(volatile int*)&g_ready) { }
        }
        __syncthreads();
    }

    // ---- SS_out over the complement of the box ----
    float acc = 0.0f;
    for (int item = blockIdx.x; item < NPLANES * 8; item += NBLOCKS_B) {
        const int p   = item >> 3;
        const int seg = item & 7;
        const int b   = p / S;
        const int d   = p - b * S;
        const int loD = g_lo[b][0], hiD = g_hi[b][0];
        const int loH = g_lo[b][1], hiH = g_hi[b][1];
        const int loW = g_lo[b][2], hiW = g_hi[b][2];
        const float4* P4 = (const float4*)pred  + (size_t)p * PLANE4;
        const float4* T4 = (const float4*)truth + (size_t)p * PLANE4;

        if (d < loD || d >= hiD) {
            // whole plane outside: this seg covers quads [seg*800, seg*800+800)
            const int end = seg * 800 + 800;
            for (int i = seg * 800 + tid; i < end; i += 256) {
                float4 pv = P4[i], tv = T4[i];
                float dx = pv.x - tv.x, dy = pv.y - tv.y, dz = pv.z - tv.z, dw = pv.w - tv.w;
                acc = fmaf(dx, dx, acc);
                acc = fmaf(dy, dy, acc);
                acc = fmaf(dz, dz, acc);
                acc = fmaf(dw, dw, acc);
            }
        } else if (seg == 0) {
            // boundary rows (outside H range)
            const int nOutH = loH + (S - hiH);
            for (int j = tid; j < nOutH * 40; j += 256) {
                int k = j / 40, cc = j - k * 40;
                int h = (k < loH) ? k : hiH + (k - loH);
                int idx = h * 40 + cc;
                float4 pv = P4[idx], tv = T4[idx];
                float dx = pv.x - tv.x, dy = pv.y - tv.y, dz = pv.z - tv.z, dw = pv.w - tv.w;
                acc = fmaf(dx, dx, acc);
                acc = fmaf(dy, dy, acc);
                acc = fmaf(dz, dz, acc);
                acc = fmaf(dw, dw, acc);
            }
            // W stubs of inside rows
            const int nStub = loW + (S - hiW);
            const int nInH  = hiH - loH;
            const float* Pp = (const float*)P4;
            const float* Tp = (const float*)T4;
            for (int j = tid; j < nInH * nStub; j += 256) {
                int r = j / nStub, s = j - r * nStub;
                int h = loH + r;
                int w = (s < loW) ? s : hiW + (s - loW);
                float dv = Pp[h * S + w] - Tp[h * S + w];
                acc = fmaf(dv, dv, acc);
            }
        }
    }

    #pragma unroll
    for (int off = 16; off > 0; off >>= 1)
        acc += __shfl_xor_sync(0xFFFFFFFFu, acc, off);
    if ((tid & 31) == 0) warpSum[tid >> 5] = (double)acc;
    __syncthreads();
    if (tid == 0) {
        double s = 0.0;
        #pragma unroll
        for (int w = 0; w < 8; w++) s += warpSum[w];
        atomicAdd(&g_ss_out, s);
    }

    // ---- last block: finalize + reset ALL scratch for the next replay ----
    __threadfence();
    if (tid == 0) sLast = (atomicAdd(&g_done_B, 1u) == (unsigned)(NBLOCKS_B - 1));
    __syncthreads();
    if (sLast) {
        if (tid == 0) {
            double sa = atomicAdd(&g_ss_all, 0.0);
            double so = atomicAdd(&g_ss_out, 0.0);
            out[0] = (float)((sa - 0.99 * so) / TOTAL_ELEMS);
            g_ss_all = 0.0; g_ss_out = 0.0;
            g_done_A = 0u; g_done_pB = 0u; g_done_B = 0u;
            g_fallback = 0;
            *(volatile int*)&g_ready = 0;
        }
        if (tid < 32) {
            ((unsigned char*)g_winD)[tid] = 0;
            ((unsigned char*)g_winH)[tid] = 0;
            ((unsigned char*)g_winW)[tid] = 0;
        }
        int* pz = (int*)g_any;                    // 1920 bytes = 480 ints
        for (int i = tid; i < (NB * 3 * S) / 4; i += 256) pz[i] = 0;
    }
}

extern "C" void kernel_launch(void* const* d_in, const int* in_sizes, int n_in,
                              void* d_out, int out_size) {
    const float* y_pred = (const float*)d_in[0];
    const float* y_true = (const float*)d_in[1];
    const int*   mask   = (const int*)d_in[2];
    float* out = (float*)d_out;

    kA<<<NPLANES, 256>>>(y_pred, y_true, mask);
    kB<<<NBLOCKS_B, 256>>>(y_pred, y_true, mask, out);
}

// round 9
// speedup vs baseline: 1.1211x; 1.1211x over previous
#include <cuda_runtime.h>
#include <cuda_bf16.h>

// Problem geometry: [B=4, 1, D=160, H=160, W=160]
#define NB 4
#define S  160
#define PLANE4      6400           // float4/int4 per (b,d) plane
#define NPLANES     640
#define MAIN_CHUNKS 5120           // fallback mask chunks (8 per plane)
#define CHUNK4      800
#define NBLOCKS_B   148            // 1/SM -> co-resident (fallback spin safe)
#define TOTAL_ELEMS (4.0 * 160.0 * 160.0 * 160.0)

// ---- device scratch (zero at load; finalizer re-zeroes what needs it) ----
__device__ unsigned char g_winD[NB][8];   // boundary-slab any-flags (0..3 low, 4..7 high)
__device__ unsigned char g_winH[NB][8];
__device__ unsigned char g_winW[NB][8];
__device__ unsigned char g_any[NB][3][S]; // full projections (fallback only)
__device__ double g_planeSS[NPLANES];     // per-plane sum of (p-t)^2
__device__ float  g_row159[NPLANES];      // per-plane sum over row h=159
__device__ float  g_col159[NPLANES];      // per-plane sum over column w=159
__device__ float  g_e1599[NPLANES];       // per-plane element (h=159,w=159)
__device__ int    g_lo[NB][3];
__device__ int    g_hi[NB][3];
__device__ int    g_ready;
__device__ double g_ss_out;
__device__ unsigned g_done_pB, g_done_B;

// Exact f32 replication of the reference bbox math (mn<0 -> empty box).
__device__ __forceinline__ void bbox_from(int mn, int mx, int* lo, int* hi) {
    if (mn < 0) { *lo = 0; *hi = 0; return; }
    float c = ((float)mx + (float)mn) * 0.5f;
    float e = ((float)mx - (float)mn + 1.0f) * 0.5f * 1.2f;   // EXPAND
    *lo = (int)fmaxf(0.0f, floorf(c - e));
    *hi = (int)fminf((float)(S - 1), floorf(c + e));          // EXCLUSIVE
}

// ===================== kernel A: per-plane SS + slab scalars + windows ======
// One block per (b,d) plane, 640 x 256. During the single streaming pass it
// accumulates: full plane SS, row-159 SS, col-159 SS, and e(159,159). It also
// reads its plane's mask boundary windows (H rows 0-3/156-159; W first/last
// int4 per row), and blocks 0..255 each scan one 800-int4 chunk of the 32
// D-boundary mask planes. All flag stores are benign races (writers store 1).
__global__ __launch_bounds__(256) void kA(const float* __restrict__ pred,
                                          const float* __restrict__ truth,
                                          const int*   __restrict__ mask) {
    __shared__ double wAcc[8], wRow[8], wCol[8];
    __shared__ int sw[8];

    const int p   = blockIdx.x;          // 0..639
    const int b   = p / S;
    const int tid = threadIdx.x;

    if (tid < 8) sw[tid] = 0;
    __syncthreads();

    // ---- mask boundary windows (issued first so loads overlap the SS pass) --
    const int4* M = (const int4*)mask + (size_t)p * PLANE4;
    if (tid < 160) {
        // H window: rows 0..3 (quads 0..159) and 156..159 (quads 6240..6399)
        int4 va = M[tid];
        int4 vb = M[6240 + tid];
        if (va.x | va.y | va.z | va.w) g_winH[b][tid / 40]     = 1;
        if (vb.x | vb.y | vb.z | vb.w) g_winH[b][4 + tid / 40] = 1;
        // W window: first/last int4 of row tid
        int4 v0 = M[tid * 40];           // w 0..3
        int4 v1 = M[tid * 40 + 39];      // w 156..159
        if (v0.x) sw[0] = 1;
        if (v0.y) sw[1] = 1;
        if (v0.z) sw[2] = 1;
        if (v0.w) sw[3] = 1;
        if (v1.x) sw[4] = 1;
        if (v1.y) sw[5] = 1;
        if (v1.z) sw[6] = 1;
        if (v1.w) sw[7] = 1;
    }
    // D window: distributed — blocks 0..255 scan one chunk of a boundary plane
    if (blockIdx.x < 256) {
        int item = blockIdx.x;
        int bb   = item >> 6;
        int wp   = (item >> 3) & 7;
        int part = item & 7;
        int dd   = (wp < 4) ? wp : 152 + wp;
        const int4* MD = (const int4*)mask + (size_t)(bb * S + dd) * PLANE4 + part * CHUNK4;
        int o = 0;
        for (int j = tid; j < CHUNK4; j += 256) {
            int4 v = MD[j];
            o |= v.x | v.y | v.z | v.w;
        }
        if (__syncthreads_or(o)) { if (tid == 0) g_winD[bb][wp] = 1; }
    }

    // ---- streaming SS pass over this pred/true plane ----
    const float4* P = (const float4*)pred  + (size_t)p * PLANE4;
    const float4* T = (const float4*)truth + (size_t)p * PLANE4;

    bool isW[5];                         // (i % 40 == 39) is j-invariant per slot
    #pragma unroll
    for (int s = 0; s < 5; s++) isW[s] = (((tid + 16 * s) % 40) == 39);

    float acc = 0.0f, accRow = 0.0f, accCol = 0.0f, e1599 = 0.0f;
    #pragma unroll 1
    for (int j = 0; j < 5; j++) {
        #pragma unroll
        for (int s = 0; s < 5; s++) {
            int i = tid + 256 * (j * 5 + s);
            float4 pv = P[i];
            float4 tv = T[i];
            float dx = pv.x - tv.x, dy = pv.y - tv.y;
            float dz = pv.z - tv.z, dw = pv.w - tv.w;
            float q = dx * dx;
            q = fmaf(dy, dy, q);
            q = fmaf(dz, dz, q);
            q = fmaf(dw, dw, q);
            acc += q;
            if (i >= 6360) accRow += q;          // row h = 159
            if (isW[s]) {                         // column w = 159 (.w lane)
                float w2 = dw * dw;
                accCol += w2;
                if (i == 6399) e1599 = w2;        // (h=159, w=159)
            }
        }
    }

    __syncthreads();
    if (tid < 8 && sw[tid]) g_winW[b][tid] = 1;

    // ---- reduce the three accumulators; store per-plane scalars ----
    #pragma unroll
    for (int off = 16; off > 0; off >>= 1) {
        acc    += __shfl_xor_sync(0xFFFFFFFFu, acc,    off);
        accRow += __shfl_xor_sync(0xFFFFFFFFu, accRow, off);
        accCol += __shfl_xor_sync(0xFFFFFFFFu, accCol, off);
    }
    int lane = tid & 31, wid = tid >> 5;
    if (lane == 0) {
        wAcc[wid] = (double)acc;
        wRow[wid] = (double)accRow;
        wCol[wid] = (double)accCol;
    }
    __syncthreads();
    if (tid == 0) {
        double sa = 0.0, sr = 0.0, sc = 0.0;
        #pragma unroll
        for (int w = 0; w < 8; w++) { sa += wAcc[w]; sr += wRow[w]; sc += wCol[w]; }
        g_planeSS[p] = sa;
        g_row159[p]  = (float)sr;
        g_col159[p]  = (float)sc;
    }
    if (tid == 255) g_e1599[p] = e1599;  // thread that owns i=6399
}

// ===================== kernel B: tiny algebra (or rare general fallback) ====
// If every axis of every batch has fg in both 4-wide boundary windows, the
// reference box is provably [0,159)^3, so the complement is the three
// index-159 slabs and SS_out follows by inclusion-exclusion over kA's
// per-plane scalars — block 0 alone does ~13KB of table reads. Otherwise the
// exact general fallback runs (full projection + complement).
__global__ __launch_bounds__(256) void kB(const float* __restrict__ pred,
                                          const float* __restrict__ truth,
                                          const int*   __restrict__ mask,
                                          float* __restrict__ out) {
    __shared__ int sFb;
    __shared__ double sRed[8][8];
    __shared__ double warpSum[8];
    __shared__ int sLast;
    const int tid = threadIdx.x;

    if (tid == 0) {
        int f = 0;
        for (int bb = 0; bb < NB; bb++) {
            volatile unsigned char* wA[3] = { g_winD[bb], g_winH[bb], g_winW[bb] };
            for (int ax = 0; ax < 3; ax++) {
                int loAny = wA[ax][0] | wA[ax][1] | wA[ax][2] | wA[ax][3];
                int hiAny = wA[ax][4] | wA[ax][5] | wA[ax][6] | wA[ax][7];
                if (!loAny || !hiAny) f = 1;
            }
        }
        sFb = f;
    }
    __syncthreads();

    if (!sFb) {
        if (blockIdx.x != 0) return;
        // ---- resolved: box = [0,159)^3; inclusion-exclusion over tables ----
        double v[8];                     // ssAll, A, B, C, AB, AC, BC, ABC
        #pragma unroll
        for (int q = 0; q < 8; q++) v[q] = 0.0;
        for (int p = tid; p < NPLANES; p += 256) {
            double ps = g_planeSS[p];
            double r  = (double)g_row159[p];
            double c  = (double)g_col159[p];
            double e  = (double)g_e1599[p];
            v[0] += ps; v[2] += r; v[3] += c; v[6] += e;
            if ((p % S) == S - 1) { v[1] += ps; v[4] += r; v[5] += c; v[7] += e; }
        }
        #pragma unroll
        for (int q = 0; q < 8; q++) {
            #pragma unroll
            for (int off = 16; off > 0; off >>= 1)
                v[q] += __shfl_xor_sync(0xFFFFFFFFu, v[q], off);
        }
        int lane = tid & 31, wid = tid >> 5;
        if (lane == 0) {
            #pragma unroll
            for (int q = 0; q < 8; q++) sRed[wid][q] = v[q];
        }
        __syncthreads();
        if (tid == 0) {
            double t[8];
            #pragma unroll
            for (int q = 0; q < 8; q++) {
                t[q] = 0.0;
                #pragma unroll
                for (int w = 0; w < 8; w++) t[q] += sRed[w][q];
            }
            double ssOut = t[1] + t[2] + t[3] - t[4] - t[5] - t[6] + t[7];
            out[0] = (float)((t[0] - 0.99 * ssOut) / TOTAL_ELEMS);
        }
        // reset scratch for the next graph replay (block 0's threads)
        if (tid < 96) {
            ((unsigned char*)g_winD)[tid < 32 ? tid : 0] = 0;  // overwritten below
        }
        if (tid < 32) {
            ((unsigned char*)g_winD)[tid] = 0;
            ((unsigned char*)g_winH)[tid] = 0;
            ((unsigned char*)g_winW)[tid] = 0;
        }
        {
            int* pz = (int*)g_any;       // 1920 bytes = 480 ints
            for (int i = tid; i < (NB * 3 * S) / 4; i += 256) pz[i] = 0;
        }
        if (tid == 0) {
            g_ss_out = 0.0; g_done_pB = 0u; g_done_B = 0u; g_ready = 0;
        }
        return;
    }

    // ======================= rare general fallback ==========================
    // 148 co-resident blocks: full mask projection -> exact bbox -> complement.
    {
        const int rg = tid / 40, c = tid % 40;
        for (int chunk = blockIdx.x; chunk < MAIN_CHUNKS; chunk += NBLOCKS_B) {
            if (tid < 160) {
                int plane = chunk >> 3, part = chunk & 7;
                int b = plane / S, d = plane - b * S;
                const int4* M = (const int4*)mask + plane * PLANE4 + part * CHUNK4 + tid;
                int4 o = make_int4(0, 0, 0, 0);
                #pragma unroll
                for (int k = 0; k < 5; k++) {
                    int4 v = M[160 * k];
                    o.x |= v.x; o.y |= v.y; o.z |= v.z; o.w |= v.w;
                    if (v.x | v.y | v.z | v.w) {
                        g_any[b][1][part * 20 + rg + 4 * k] = 1;
                        g_any[b][0][d] = 1;
                    }
                }
                if (o.x) g_any[b][2][c * 4 + 0] = 1;
                if (o.y) g_any[b][2][c * 4 + 1] = 1;
                if (o.z) g_any[b][2][c * 4 + 2] = 1;
                if (o.w) g_any[b][2][c * 4 + 3] = 1;
            }
        }
        __threadfence();
        if (tid == 0) {
            if (atomicAdd(&g_done_pB, 1u) == (unsigned)(NBLOCKS_B - 1)) {
                for (int b = 0; b < NB; b++)
                    for (int ax = 0; ax < 3; ax++) {
                        volatile unsigned char* a = &g_any[b][ax][0];
                        int mn = -1, mx = -1;
                        for (int i = 0; i < S; i++)
                            if (a[i]) { if (mn < 0) mn = i; mx = i; }
                        int lo, hi;
                        bbox_from(mn, mx, &lo, &hi);
                        g_lo[b][ax] = lo; g_hi[b][ax] = hi;
                    }
                __threadfence();
                *(volatile int*)&g_ready = 1;
            }
            while (!*(volatile int*)&g_ready) { }
        }
        __syncthreads();
    }

    // SS_out over the general complement
    float acc = 0.0f;
    for (int item = blockIdx.x; item < NPLANES * 8; item += NBLOCKS_B) {
        const int p   = item >> 3;
        const int seg = item & 7;
        const int b   = p / S;
        const int d   = p - b * S;
        const int loD = g_lo[b][0], hiD = g_hi[b][0];
        const int loH = g_lo[b][1], hiH = g_hi[b][1];
        const int loW = g_lo[b][2], hiW = g_hi[b][2];
        const float4* P4 = (const float4*)pred  + (size_t)p * PLANE4;
        const float4* T4 = (const float4*)truth + (size_t)p * PLANE4;

        if (d < loD || d >= hiD) {
            const int end = seg * 800 + 800;
            for (int i = seg * 800 + tid; i < end; i += 256) {
                float4 pv = P4[i], tv = T4[i];
                float dx = pv.x - tv.x, dy = pv.y - tv.y, dz = pv.z - tv.z, dw = pv.w - tv.w;
                acc = fmaf(dx, dx, acc);
                acc = fmaf(dy, dy, acc);
                acc = fmaf(dz, dz, acc);
                acc = fmaf(dw, dw, acc);
            }
        } else if (seg == 0) {
            const int nOutH = loH + (S - hiH);
            for (int j = tid; j < nOutH * 40; j += 256) {
                int k = j / 40, cc = j - k * 40;
                int h = (k < loH) ? k : hiH + (k - loH);
                int idx = h * 40 + cc;
                float4 pv = P4[idx], tv = T4[idx];
                float dx = pv.x - tv.x, dy = pv.y - tv.y, dz = pv.z - tv.z, dw = pv.w - tv.w;
                acc = fmaf(dx, dx, acc);
                acc = fmaf(dy, dy, acc);
                acc = fmaf(dz, dz, acc);
                acc = fmaf(dw, dw, acc);
            }
            const int nStub = loW + (S - hiW);
            const int nInH  = hiH - loH;
            const float* Pp = (const float*)P4;
            const float* Tp = (const float*)T4;
            for (int j = tid; j < nInH * nStub; j += 256) {
                int r = j / nStub, s = j - r * nStub;
                int h = loH + r;
                int w = (s < loW) ? s : hiW + (s - loW);
                float dv = Pp[h * S + w] - Tp[h * S + w];
                acc = fmaf(dv, dv, acc);
            }
        }
    }

    #pragma unroll
    for (int off = 16; off > 0; off >>= 1)
        acc += __shfl_xor_sync(0xFFFFFFFFu, acc, off);
    if ((tid & 31) == 0) warpSum[tid >> 5] = (double)acc;
    __syncthreads();
    if (tid == 0) {
        double s = 0.0;
        #pragma unroll
        for (int w = 0; w < 8; w++) s += warpSum[w];
        atomicAdd(&g_ss_out, s);
    }

    __threadfence();
    if (tid == 0) sLast = (atomicAdd(&g_done_B, 1u) == (unsigned)(NBLOCKS_B - 1));
    __syncthreads();
    if (sLast) {
        // SS_all from the planeSS table (parallel)
        double sa = 0.0;
        for (int p = tid; p < NPLANES; p += 256) sa += g_planeSS[p];
        #pragma unroll
        for (int off = 16; off > 0; off >>= 1)
            sa += __shfl_xor_sync(0xFFFFFFFFu, sa, off);
        if ((tid & 31) == 0) warpSum[tid >> 5] = sa;
        __syncthreads();
        if (tid == 0) {
            double total = 0.0;
            #pragma unroll
            for (int w = 0; w < 8; w++) total += warpSum[w];
            double so = atomicAdd(&g_ss_out, 0.0);
            out[0] = (float)((total - 0.99 * so) / TOTAL_ELEMS);
            g_ss_out = 0.0; g_done_pB = 0u; g_done_B = 0u; g_ready = 0;
        }
        if (tid < 32) {
            ((unsigned char*)g_winD)[tid] = 0;
            ((unsigned char*)g_winH)[tid] = 0;
            ((unsigned char*)g_winW)[tid] = 0;
        }
        int* pz = (int*)g_any;
        for (int i = tid; i < (NB * 3 * S) / 4; i += 256) pz[i] = 0;
    }
}

extern "C" void kernel_launch(void* const* d_in, const int* in_sizes, int n_in,
                              void* d_out, int out_size) {
    const float* y_pred = (const float*)d_in[0];
    const float* y_true = (const float*)d_in[1];
    const int*   mask   = (const int*)d_in[2];
    float* out = (float*)d_out;

    kA<<<NPLANES, 256>>>(y_pred, y_true, mask);
    kB<<<NBLOCKS_B, 256>>>(y_pred, y_true, mask, out);
}

// round 11
// speedup vs baseline: 1.2536x; 1.1181x over previous
#include <cuda_runtime.h>
#include <cuda_bf16.h>

// Problem geometry: [B=4, 1, D=160, H=160, W=160]
#define NB 4
#define S  160
#define PLANE4  6400               // float4/int4 per (b,d) plane
#define NPLANES 640
#define CHUNK4  800
#define N4      4096000            // total float4 quads
#define BATCH4  1024000            // quads per batch
#define TOTAL_ELEMS (4.0 * 160.0 * 160.0 * 160.0)

// ---- device scratch (zero at load; last block re-zeroes flags/counter) ----
__device__ unsigned char g_winD[NB][8];   // boundary-slab any-flags (0..3 low, 4..7 high)
__device__ unsigned char g_winH[NB][8];
__device__ unsigned char g_winW[NB][8];
__device__ double g_planeSS[NPLANES];     // per-plane sum of (p-t)^2
__device__ float  g_row159[NPLANES];      // per-plane sum over row h=159
__device__ float  g_col159[NPLANES];      // per-plane sum over col w=159
__device__ float  g_e1599[NPLANES];       // per-plane element (159,159)
__device__ unsigned g_done;

// Exact f32 replication of the reference bbox math (mn<0 -> empty box).
__device__ __forceinline__ void bbox_from(int mn, int mx, int* lo, int* hi) {
    if (mn < 0) { *lo = 0; *hi = 0; return; }
    float c = ((float)mx + (float)mn) * 0.5f;
    float e = ((float)mx - (float)mn + 1.0f) * 0.5f * 1.2f;   // EXPAND
    *lo = (int)fmaxf(0.0f, floorf(c - e));
    *hi = (int)fminf((float)(S - 1), floorf(c + e));          // EXCLUSIVE
}

// ============================================================================
// Single kernel. One block per (b,d) plane, 640 x 256.
// Per-block: mask boundary windows + streaming SS with row/col/corner slabs.
// Last-done block: if every axis has fg in both 4-wide boundary windows, the
// reference box is PROVABLY [0,159)^3 (mn<=3, mx>=156 => c-e<0, c+e>159), so
// the ROI complement is exactly the three index-159 slabs and the loss follows
// by inclusion-exclusion over the per-plane tables. Otherwise a single-block
// exact fallback (full mask bbox + full weighted pass) runs — never taken for
// dense masks, but keeps the kernel correct for ALL inputs.
// ============================================================================
__global__ __launch_bounds__(256) void k_all(const float* __restrict__ pred,
                                             const float* __restrict__ truth,
                                             const int*   __restrict__ mask,
                                             float* __restrict__ out) {
    __shared__ double wAcc[8], wRow[8], wCol[8];
    __shared__ int sw[8];
    __shared__ int sLast;
    __shared__ unsigned char sFlags[96];
    __shared__ double sRed[8][8];

    const int p   = blockIdx.x;          // 0..639
    const int b   = p / S;
    const int tid = threadIdx.x;

    if (tid < 8) sw[tid] = 0;
    __syncthreads();

    // ---- mask boundary windows ----
    const int4* M = (const int4*)mask + (size_t)p * PLANE4;
    if (tid < 160) {
        // H window: rows 0..3 (quads 0..159) and 156..159 (quads 6240..6399)
        int4 va = M[tid];
        int4 vb = M[6240 + tid];
        if (va.x | va.y | va.z | va.w) g_winH[b][tid / 40]     = 1;
        if (vb.x | vb.y | vb.z | vb.w) g_winH[b][4 + tid / 40] = 1;
        // W window: first/last int4 of row tid
        int4 v0 = M[tid * 40];           // w 0..3
        int4 v1 = M[tid * 40 + 39];      // w 156..159
        if (v0.x) sw[0] = 1;
        if (v0.y) sw[1] = 1;
        if (v0.z) sw[2] = 1;
        if (v0.w) sw[3] = 1;
        if (v1.x) sw[4] = 1;
        if (v1.y) sw[5] = 1;
        if (v1.z) sw[6] = 1;
        if (v1.w) sw[7] = 1;
    }
    // D window: blocks 0..255 each scan one 800-int4 chunk of a boundary plane
    if (blockIdx.x < 256) {
        int item = blockIdx.x;
        int bb   = item >> 6;
        int wp   = (item >> 3) & 7;
        int part = item & 7;
        int dd   = (wp < 4) ? wp : 152 + wp;
        const int4* MD = (const int4*)mask + (size_t)(bb * S + dd) * PLANE4 + part * CHUNK4;
        int o = 0;
        for (int j = tid; j < CHUNK4; j += 256) {
            int4 v = MD[j];
            o |= v.x | v.y | v.z | v.w;
        }
        if (__syncthreads_or(o)) { if (tid == 0) g_winD[bb][wp] = 1; }
    }

    // ---- streaming SS pass over this plane (25 iters = 5x5) ----
    const float4* P = (const float4*)pred  + (size_t)p * PLANE4;
    const float4* T = (const float4*)truth + (size_t)p * PLANE4;

    bool isW[5];                         // (i % 40 == 39): j-invariant per slot
    #pragma unroll
    for (int s = 0; s < 5; s++) isW[s] = (((tid + 16 * s) % 40) == 39);

    float acc = 0.0f, accRow = 0.0f, accCol = 0.0f, e1599 = 0.0f;
    #pragma unroll 1
    for (int j = 0; j < 5; j++) {
        #pragma unroll
        for (int s = 0; s < 5; s++) {
            int i = tid + 256 * (j * 5 + s);
            float4 pv = P[i];
            float4 tv = T[i];
            float dx = pv.x - tv.x, dy = pv.y - tv.y;
            float dz = pv.z - tv.z, dw = pv.w - tv.w;
            float q = dx * dx;
            q = fmaf(dy, dy, q);
            q = fmaf(dz, dz, q);
            q = fmaf(dw, dw, q);
            acc += q;
            if (i >= 6360) accRow += q;           // row h = 159
            if (isW[s]) {                          // column w = 159 (.w lane)
                float w2 = dw * dw;
                accCol += w2;
                if (i == 6399) e1599 = w2;         // (159,159)
            }
        }
    }

    __syncthreads();
    if (tid < 8 && sw[tid]) g_winW[b][tid] = 1;

    // ---- reduce; store per-plane tables ----
    #pragma unroll
    for (int off = 16; off > 0; off >>= 1) {
        acc    += __shfl_xor_sync(0xFFFFFFFFu, acc,    off);
        accRow += __shfl_xor_sync(0xFFFFFFFFu, accRow, off);
        accCol += __shfl_xor_sync(0xFFFFFFFFu, accCol, off);
    }
    const int lane = tid & 31, wid = tid >> 5;
    if (lane == 0) {
        wAcc[wid] = (double)acc;
        wRow[wid] = (double)accRow;
        wCol[wid] = (double)accCol;
    }
    __syncthreads();
    if (tid == 0) {
        double sa = 0.0, sr = 0.0, sc = 0.0;
        #pragma unroll
        for (int w = 0; w < 8; w++) { sa += wAcc[w]; sr += wRow[w]; sc += wCol[w]; }
        g_planeSS[p] = sa;
        g_row159[p]  = (float)sr;
        g_col159[p]  = (float)sc;
    }
    if (tid == 255) g_e1599[p] = e1599;

    // ---- threadFenceReduction ticket: last-done block finalizes ----
    __threadfence();
    __syncthreads();
    if (tid == 0) sLast = (atomicAdd(&g_done, 1u) == (unsigned)(NPLANES - 1));
    __syncthreads();
    if (!sLast) return;

    // parallel window-flag fetch (96 loads in flight, not 96 serial ones)
    if (tid < 32)       sFlags[tid]      = ((const unsigned char*)g_winD)[tid];
    else if (tid < 64)  sFlags[tid]      = ((const unsigned char*)g_winH)[tid - 32];
    else if (tid < 96)  sFlags[tid]      = ((const unsigned char*)g_winW)[tid - 64];
    __syncthreads();

    bool resolved = true;
    #pragma unroll
    for (int bb = 0; bb < NB; bb++) {
        #pragma unroll
        for (int ax = 0; ax < 3; ax++) {
            const unsigned char* f = &sFlags[ax * 32 + bb * 8];
            int loAny = f[0] | f[1] | f[2] | f[3];
            int hiAny = f[4] | f[5] | f[6] | f[7];
            if (!loAny || !hiAny) resolved = false;
        }
    }

    if (resolved) {
        // box = [0,159)^3 for every batch: inclusion-exclusion over tables
        double v[8];                     // ssAll, D, H, W, DH, DW, HW, DHW
        #pragma unroll
        for (int q = 0; q < 8; q++) v[q] = 0.0;
        for (int pp = tid; pp < NPLANES; pp += 256) {
            double ps = g_planeSS[pp];
            double r  = (double)g_row159[pp];
            double c  = (double)g_col159[pp];
            double e  = (double)g_e1599[pp];
            v[0] += ps; v[2] += r; v[3] += c; v[6] += e;
            if ((pp % S) == S - 1) { v[1] += ps; v[4] += r; v[5] += c; v[7] += e; }
        }
        #pragma unroll
        for (int q = 0; q < 8; q++) {
            #pragma unroll
            for (int off = 16; off > 0; off >>= 1)
                v[q] += __shfl_xor_sync(0xFFFFFFFFu, v[q], off);
        }
        if (lane == 0) {
            #pragma unroll
            for (int q = 0; q < 8; q++) sRed[wid][q] = v[q];
        }
        __syncthreads();
        if (tid == 0) {
            double t[8];
            #pragma unroll
            for (int q = 0; q < 8; q++) {
                t[q] = 0.0;
                #pragma unroll
                for (int w = 0; w < 8; w++) t[q] += sRed[w][q];
            }
            double ssOut = t[1] + t[2] + t[3] - t[4] - t[5] - t[6] + t[7];
            out[0] = (float)((t[0] - 0.99 * ssOut) / TOTAL_ELEMS);
        }
    } else {
        // ---- exact single-block fallback (correctness path; never taken for
        //      dense masks): bbox via shared atomic min/max, then full
        //      weighted pass ----
        __shared__ int sMn[12], sMx[12];
        if (tid < 12) { sMn[tid] = S; sMx[tid] = -1; }
        __syncthreads();

        const int4* MM = (const int4*)mask;
        for (int i = tid; i < N4; i += 256) {
            int4 v = MM[i];
            if (v.x | v.y | v.z | v.w) {
                int bb  = i / BATCH4;
                int rem = i - bb * BATCH4;
                int d   = rem / PLANE4;
                int ip  = rem - d * PLANE4;
                int h   = ip / 40;
                int w0  = (ip - h * 40) * 4;
                atomicMin(&sMn[bb * 3 + 0], d); atomicMax(&sMx[bb * 3 + 0], d);
                atomicMin(&sMn[bb * 3 + 1], h); atomicMax(&sMx[bb * 3 + 1], h);
                if (v.x) { atomicMin(&sMn[bb * 3 + 2], w0 + 0); atomicMax(&sMx[bb * 3 + 2], w0 + 0); }
                if (v.y) { atomicMin(&sMn[bb * 3 + 2], w0 + 1); atomicMax(&sMx[bb * 3 + 2], w0 + 1); }
                if (v.z) { atomicMin(&sMn[bb * 3 + 2], w0 + 2); atomicMax(&sMx[bb * 3 + 2], w0 + 2); }
                if (v.w) { atomicMin(&sMn[bb * 3 + 2], w0 + 3); atomicMax(&sMx[bb * 3 + 2], w0 + 3); }
            }
        }
        __syncthreads();

        __shared__ int sLo[12], sHi[12];
        if (tid < 12) {
            int mn = (sMx[tid] >= 0) ? sMn[tid] : -1;
            int lo, hi;
            bbox_from(mn, sMx[tid], &lo, &hi);
            sLo[tid] = lo; sHi[tid] = hi;
        }
        __syncthreads();

        const float4* PP = (const float4*)pred;
        const float4* TT = (const float4*)truth;
        float fa = 0.0f;
        for (int i = tid; i < N4; i += 256) {
            float4 pv = PP[i];
            float4 tv = TT[i];
            int bb  = i / BATCH4;
            int rem = i - bb * BATCH4;
            int d   = rem / PLANE4;
            int ip  = rem - d * PLANE4;
            int h   = ip / 40;
            int w0  = (ip - h * 40) * 4;
            bool inDH = (d >= sLo[bb * 3]) && (d < sHi[bb * 3]) &&
                        (h >= sLo[bb * 3 + 1]) && (h < sHi[bb * 3 + 1]);
            int loW = sLo[bb * 3 + 2], hiW = sHi[bb * 3 + 2];
            float wx = (inDH && w0 + 0 >= loW && w0 + 0 < hiW) ? 1.0f : 0.01f;
            float wy = (inDH && w0 + 1 >= loW && w0 + 1 < hiW) ? 1.0f : 0.01f;
            float wz = (inDH && w0 + 2 >= loW && w0 + 2 < hiW) ? 1.0f : 0.01f;
            float ww = (inDH && w0 + 3 >= loW && w0 + 3 < hiW) ? 1.0f : 0.01f;
            float dx = pv.x - tv.x, dy = pv.y - tv.y, dz = pv.z - tv.z, dw = pv.w - tv.w;
            fa = fmaf(wx * dx, dx, fa);
            fa = fmaf(wy * dy, dy, fa);
            fa = fmaf(wz * dz, dz, fa);
            fa = fmaf(ww * dw, dw, fa);
        }
        #pragma unroll
        for (int off = 16; off > 0; off >>= 1)
            fa += __shfl_xor_sync(0xFFFFFFFFu, fa, off);
        if (lane == 0) wAcc[wid] = (double)fa;
        __syncthreads();
        if (tid == 0) {
            double s = 0.0;
            #pragma unroll
            for (int w = 0; w < 8; w++) s += wAcc[w];
            out[0] = (float)(s / TOTAL_ELEMS);
        }
    }

    // ---- reset scratch so the next graph replay starts from a clean state --
    __syncthreads();
    if (tid < 32) {
        ((unsigned char*)g_winD)[tid] = 0;
        ((unsigned char*)g_winH)[tid] = 0;
        ((unsigned char*)g_winW)[tid] = 0;
    }
    if (tid == 0) g_done = 0u;
}

extern "C" void kernel_launch(void* const* d_in, const int* in_sizes, int n_in,
                              void* d_out, int out_size) {
    const float* y_pred = (const float*)d_in[0];
    const float* y_true = (const float*)d_in[1];
    const int*   mask   = (const int*)d_in[2];
    float* out = (float*)d_out;

    k_all<<<NPLANES, 256>>>(y_pred, y_true, mask, out);
}